// round 5
// baseline (speedup 1.0000x reference)
#include <cuda_runtime.h>
#include <cstdint>
#include <math.h>

// Problem constants
#define BATCH   32
#define SEQT    512
#define DIN     512
#define HID     512
#define LAYERS  2
#define G4      (4*HID)          // 2048 gate rows per layer

// Persistent-kernel config
#define NCTA    128              // 64 CTAs per layer
#define THREADS 256              // 8 warps; warp w owns hidden index jbase+w
#define JPC     8                // hidden indices per CTA (64*8 = 512 per layer)
#define KT      128              // k-chunk staged in SMEM per step

// SMEM floats: wx(32*512) + wh(32*512) + in0(KT*32) + in1(KT*32) + bias(32)
#define SMEM_FLOATS (16384 + 16384 + (KT*32) + (KT*32) + 32)
#define SMEM_BYTES  (SMEM_FLOATS * 4)

// ---------------- device scratch (static: no allocation allowed) -------------
__device__ float   g_xT[SEQT * DIN * BATCH];         // x transposed: [t][k][b]  (32 MB)
__device__ float   g_h[LAYERS][2][HID * BATCH];      // ping-pong h: [layer][parity][j*32+b]
__device__ unsigned g_arrive;
__device__ unsigned g_release;

// ---------------- reset barrier state (fresh per launch) ---------------------
__global__ void reset_kernel() {
    g_arrive  = 0u;
    g_release = 0u;
}

// ---------------- transpose x: [B][T][D] -> xT[t][k][b] ----------------------
__global__ void transpose_x_kernel(const float* __restrict__ x) {
    __shared__ float tile[32][33];
    int t  = blockIdx.x;
    int k0 = blockIdx.y * 32;
    int lx = threadIdx.x;            // 0..31
    // read: coalesced along k
    for (int bb = threadIdx.y; bb < 32; bb += 8)
        tile[bb][lx] = x[((bb * SEQT + t) * DIN) + k0 + lx];
    __syncthreads();
    // write: coalesced along b
    for (int kk = threadIdx.y; kk < 32; kk += 8)
        g_xT[(t * DIN + (k0 + kk)) * BATCH + lx] = tile[lx][kk];
}

// ---------------- grid-wide barrier (release/acquire hardened) ---------------
__device__ __forceinline__ void grid_barrier(unsigned gen) {
    __syncthreads();
    __threadfence();                 // every thread releases its global stores
    __syncthreads();                 // ... before thread 0 arrives
    if (threadIdx.x == 0) {
        unsigned a = atomicAdd(&g_arrive, 1u);
        unsigned target = gen * (unsigned)NCTA;
        if (a + 1u == target) {
            atomicExch(&g_release, gen);
        } else {
            while (*(volatile unsigned*)&g_release < gen) { }
        }
        __threadfence();             // acquire
    }
    __syncthreads();
}

__device__ __forceinline__ float sigmoidf_(float v) {
    return 1.0f / (1.0f + expf(-v));
}

// .cg (L2-coherent) 128-bit load/store for cross-CTA h traffic
__device__ __forceinline__ float4 ldcg4(const float4* p) { return __ldcg(p); }
__device__ __forceinline__ void   stcg (float* p, float v) { __stcg(p, v); }

// ---------------- persistent LSTM kernel -------------------------------------
__global__ void __launch_bounds__(THREADS, 1)
lstm_persist(const float* __restrict__ h0,
             const float* __restrict__ c0,
             const float* __restrict__ Wx,   // [L][4H][D]
             const float* __restrict__ bx,   // [L][4H]
             const float* __restrict__ Wh,   // [L][4H][H]
             const float* __restrict__ bh,   // [L][4H]
             float* __restrict__ out,
             int out_size) {
    extern __shared__ float smem[];
    float* s_wx   = smem;                      // [32 rows][512]   row = j_local*4 + gate
    float* s_wh   = s_wx + 32 * 512;
    float* s_in0  = s_wh + 32 * 512;           // [KT][32]
    float* s_in1  = s_in0 + KT * 32;           // [KT][32]
    float* s_bias = s_in1 + KT * 32;           // [32]

    const int cta   = blockIdx.x;
    const int l     = cta >> 6;                // 0..1
    const int jbase = (cta & 63) * JPC;
    const int tid   = threadIdx.x;
    const int w     = tid >> 5;                // warp 0..7 -> j_local
    const int lane  = tid & 31;                // batch index

    // ---- load this CTA's weight rows into SMEM (once) ----
    for (int i = tid * 4; i < 32 * 512; i += THREADS * 4) {
        int row  = i >> 9;                     // j_local*4 + g
        int k    = i & 511;
        int grow = l * G4 + (row & 3) * HID + jbase + (row >> 2);
        *(float4*)&s_wx[i] = *(const float4*)&Wx[(size_t)grow * DIN + k];
        *(float4*)&s_wh[i] = *(const float4*)&Wh[(size_t)grow * HID + k];
    }
    if (tid < 32) {
        int row  = tid;
        int grow = l * G4 + (row & 3) * HID + jbase + (row >> 2);
        s_bias[row] = bx[grow] + bh[grow];
    }

    // ---- init state: thread owns (j = jbase+w, b = lane) ----
    const int j = jbase + w;
    float c_reg  = c0[(lane * LAYERS + l) * HID + j];
    float h_last = h0[(lane * LAYERS + l) * HID + j];
    // Initial h must be visible at BOTH parities:
    //   layer 0 first reads parity 1 (phase 0), layer 1 first reads parity 0
    //   (phase 1). g_h persists across graph replays, so writing only one
    //   parity leaves stale data from the previous run in the other.
    stcg(&g_h[l][0][j * BATCH + lane], h_last);
    stcg(&g_h[l][1][j * BATCH + lane], h_last);

    grid_barrier(1u);

    // ---- wavefront phases: phase p does layer0 step t=p, layer1 step t=p-1 ----
    for (int p = 0; p <= SEQT; ++p) {
        const bool active = (l == 0) ? (p < SEQT) : (p >= 1);
        const int  t      = (l == 0) ? p : (p - 1);
        const int  rdpar  = (p + 1) & 1;       // buffer written at phase p-1 (or init)
        const int  wrpar  = p & 1;

        const float* in0 = (l == 0) ? &g_xT[(size_t)t * DIN * BATCH]
                                    : &g_h[0][rdpar][0];
        const float* in1 = &g_h[l][rdpar][0];
        const bool   in0_is_h = (l != 0);

        float accX0 = 0.f, accX1 = 0.f, accX2 = 0.f, accX3 = 0.f;
        float accH0 = 0.f, accH1 = 0.f, accH2 = 0.f, accH3 = 0.f;

        for (int kc = 0; kc < DIN; kc += KT) {
            // stage activation chunk: [KT][32], contiguous in global
            if (active) {
                for (int i = tid * 4; i < KT * 32; i += THREADS * 4) {
                    // h buffers are cross-CTA: must bypass L1 (.cg). xT is safe.
                    *(float4*)&s_in0[i] = in0_is_h
                        ? ldcg4((const float4*)&in0[kc * BATCH + i])
                        : *(const float4*)&in0[kc * BATCH + i];
                    *(float4*)&s_in1[i] = ldcg4((const float4*)&in1[kc * BATCH + i]);
                }
            }
            __syncthreads();
            if (active) {
                const int w4 = w * 4;
                #pragma unroll 2
                for (int k = 0; k < KT; k += 4) {
                    float a00 = s_in0[(k + 0) * 32 + lane];
                    float a01 = s_in0[(k + 1) * 32 + lane];
                    float a02 = s_in0[(k + 2) * 32 + lane];
                    float a03 = s_in0[(k + 3) * 32 + lane];
                    float a10 = s_in1[(k + 0) * 32 + lane];
                    float a11 = s_in1[(k + 1) * 32 + lane];
                    float a12 = s_in1[(k + 2) * 32 + lane];
                    float a13 = s_in1[(k + 3) * 32 + lane];

                    float4 x0 = *(const float4*)&s_wx[((w4 + 0) << 9) + kc + k];
                    float4 x1 = *(const float4*)&s_wx[((w4 + 1) << 9) + kc + k];
                    float4 x2 = *(const float4*)&s_wx[((w4 + 2) << 9) + kc + k];
                    float4 x3 = *(const float4*)&s_wx[((w4 + 3) << 9) + kc + k];
                    float4 h0v = *(const float4*)&s_wh[((w4 + 0) << 9) + kc + k];
                    float4 h1v = *(const float4*)&s_wh[((w4 + 1) << 9) + kc + k];
                    float4 h2v = *(const float4*)&s_wh[((w4 + 2) << 9) + kc + k];
                    float4 h3v = *(const float4*)&s_wh[((w4 + 3) << 9) + kc + k];

                    accX0 = fmaf(x0.x, a00, accX0); accX0 = fmaf(x0.y, a01, accX0);
                    accX0 = fmaf(x0.z, a02, accX0); accX0 = fmaf(x0.w, a03, accX0);
                    accX1 = fmaf(x1.x, a00, accX1); accX1 = fmaf(x1.y, a01, accX1);
                    accX1 = fmaf(x1.z, a02, accX1); accX1 = fmaf(x1.w, a03, accX1);
                    accX2 = fmaf(x2.x, a00, accX2); accX2 = fmaf(x2.y, a01, accX2);
                    accX2 = fmaf(x2.z, a02, accX2); accX2 = fmaf(x2.w, a03, accX2);
                    accX3 = fmaf(x3.x, a00, accX3); accX3 = fmaf(x3.y, a01, accX3);
                    accX3 = fmaf(x3.z, a02, accX3); accX3 = fmaf(x3.w, a03, accX3);

                    accH0 = fmaf(h0v.x, a10, accH0); accH0 = fmaf(h0v.y, a11, accH0);
                    accH0 = fmaf(h0v.z, a12, accH0); accH0 = fmaf(h0v.w, a13, accH0);
                    accH1 = fmaf(h1v.x, a10, accH1); accH1 = fmaf(h1v.y, a11, accH1);
                    accH1 = fmaf(h1v.z, a12, accH1); accH1 = fmaf(h1v.w, a13, accH1);
                    accH2 = fmaf(h2v.x, a10, accH2); accH2 = fmaf(h2v.y, a11, accH2);
                    accH2 = fmaf(h2v.z, a12, accH2); accH2 = fmaf(h2v.w, a13, accH2);
                    accH3 = fmaf(h3v.x, a10, accH3); accH3 = fmaf(h3v.y, a11, accH3);
                    accH3 = fmaf(h3v.z, a12, accH3); accH3 = fmaf(h3v.w, a13, accH3);
                }
            }
            __syncthreads();
        }

        if (active) {
            float pre_i = accX0 + accH0 + s_bias[w * 4 + 0];
            float pre_f = accX1 + accH1 + s_bias[w * 4 + 1];
            float pre_g = accX2 + accH2 + s_bias[w * 4 + 2];
            float pre_o = accX3 + accH3 + s_bias[w * 4 + 3];

            float ig = sigmoidf_(pre_i);
            float fg = sigmoidf_(pre_f);
            float gg = tanhf(pre_g);
            float og = sigmoidf_(pre_o);

            c_reg  = fg * c_reg + ig * gg;
            float hN = og * tanhf(c_reg);
            h_last = hN;

            stcg(&g_h[l][wrpar][j * BATCH + lane], hN);   // L2-coherent
            if (l == 1) {
                // output[b][t][j]
                out[((size_t)lane * SEQT + t) * HID + j] = hN;
            }
        }

        grid_barrier((unsigned)(p + 2));
    }

    // ---- final h_n / c_n:  [L][B][H] each, appended after output ----
    if (out_size >= BATCH * SEQT * HID + 2 * LAYERS * BATCH * HID) {
        float* hn = out + (size_t)BATCH * SEQT * HID;
        float* cn = hn + (size_t)LAYERS * BATCH * HID;
        hn[((size_t)l * BATCH + lane) * HID + j] = h_last;
        cn[((size_t)l * BATCH + lane) * HID + j] = c_reg;
    }
}

// ---------------- launch ------------------------------------------------------
extern "C" void kernel_launch(void* const* d_in, const int* in_sizes, int n_in,
                              void* d_out, int out_size) {
    const float* x  = (const float*)d_in[0];
    const float* h0 = (const float*)d_in[1];
    const float* c0 = (const float*)d_in[2];
    const float* Wx = (const float*)d_in[3];
    const float* bx = (const float*)d_in[4];
    const float* Wh = (const float*)d_in[5];
    const float* bh = (const float*)d_in[6];
    float* out = (float*)d_out;
    (void)in_sizes; (void)n_in;

    cudaFuncSetAttribute(lstm_persist,
                         cudaFuncAttributeMaxDynamicSharedMemorySize, SMEM_BYTES);

    reset_kernel<<<1, 1>>>();

    dim3 tb(32, 8);
    dim3 tg(SEQT, DIN / 32);
    transpose_x_kernel<<<tg, tb>>>(x);

    lstm_persist<<<NCTA, THREADS, SMEM_BYTES>>>(h0, c0, Wx, bx, Wh, bh, out, out_size);
}

// round 7
// speedup vs baseline: 1.1029x; 1.1029x over previous
#include <cuda_runtime.h>
#include <cstdint>
#include <math.h>

// Problem constants
#define BATCH   32
#define SEQT    512
#define DIN     512
#define HID     512
#define LAYERS  2
#define G4      (4*HID)

// Persistent-kernel config
#define NCTA    128              // 64 CTAs per layer
#define THREADS 512              // 16 warps: warps 0-7 = k-half A, 8-15 = k-half B
#define JPC     8                // hidden indices per CTA

// SMEM float offsets
#define OFF_WX   0                       // [32 rows][512]
#define OFF_WH   16384
#define OFF_BUF  32768                   // 4 bufs x 4096 floats (2048 float2 each)
#define OFF_RED  (32768 + 16384)         // 4096 floats (8 warps x 8 accs x 32 lanes x f2)
#define OFF_BIAS (OFF_RED + 4096)
#define SMEM_FLOATS (OFF_BIAS + 32)
#define SMEM_BYTES  (SMEM_FLOATS * 4)    // 213,248 B

// ---------------- device scratch -------------------------------------------
__device__ float    g_xT[SEQT * DIN * BATCH];      // x transposed: [t][k][b]
__device__ float    g_h[LAYERS][2][HID * BATCH];   // ping-pong h: [layer][par][j*32+b]
__device__ unsigned g_arrive;
__device__ unsigned g_release;

__global__ void reset_kernel() { g_arrive = 0u; g_release = 0u; }

// ---------------- transpose x: [B][T][D] -> xT[t][k][b] ---------------------
__global__ void transpose_x_kernel(const float* __restrict__ x) {
    __shared__ float tile[32][33];
    int t  = blockIdx.x;
    int k0 = blockIdx.y * 32;
    int lx = threadIdx.x;
    for (int bb = threadIdx.y; bb < 32; bb += 8)
        tile[bb][lx] = x[((bb * SEQT + t) * DIN) + k0 + lx];
    __syncthreads();
    for (int kk = threadIdx.y; kk < 32; kk += 8)
        g_xT[(t * DIN + (k0 + kk)) * BATCH + lx] = tile[lx][kk];
}

// ---------------- grid-wide barrier (release/acquire hardened) --------------
__device__ __forceinline__ void grid_barrier(unsigned gen) {
    __syncthreads();
    __threadfence();
    __syncthreads();
    if (threadIdx.x == 0) {
        unsigned a = atomicAdd(&g_arrive, 1u);
        unsigned target = gen * (unsigned)NCTA;
        if (a + 1u == target) {
            atomicExch(&g_release, gen);
        } else {
            while (*(volatile unsigned*)&g_release < gen) { }
        }
        __threadfence();
    }
    __syncthreads();
}

__device__ __forceinline__ float sigmoidf_(float v) {
    return 1.0f / (1.0f + expf(-v));
}

// packed f32x2 FMA: d = a*b + d (two independent fp32 lanes)
__device__ __forceinline__ void fma2(unsigned long long& d,
                                     unsigned long long a,
                                     unsigned long long b) {
    asm("fma.rn.f32x2 %0, %1, %2, %0;" : "+l"(d) : "l"(a), "l"(b));
}
__device__ __forceinline__ float2 u2f2(unsigned long long v) {
    float2 f;
    asm("mov.b64 {%0, %1}, %2;" : "=f"(f.x), "=f"(f.y) : "l"(v));
    return f;
}

struct ull2 { unsigned long long x, y; };

// ---------------- persistent LSTM kernel ------------------------------------
__global__ void __launch_bounds__(THREADS, 1)
lstm_persist(const float* __restrict__ h0,
             const float* __restrict__ c0,
             const float* __restrict__ Wx,   // [L][4H][D]
             const float* __restrict__ bx,
             const float* __restrict__ Wh,   // [L][4H][H]
             const float* __restrict__ bh,
             float* __restrict__ out,
             int out_size) {
    extern __shared__ float smem[];
    float* s_wx   = smem + OFF_WX;
    float* s_wh   = smem + OFF_WH;
    float* s_bias = smem + OFF_BIAS;

    const int cta   = blockIdx.x;
    const int l     = cta >> 6;              // layer 0/1
    const int jbase = (cta & 63) * JPC;
    const int tid   = threadIdx.x;
    const int w     = tid >> 5;              // 0..15
    const int lane  = tid & 31;              // batch index
    const int grp   = w >> 3;                // 0 = k[0,256), 1 = k[256,512)
    const int wj    = w & 7;                 // hidden index within CTA

    // ---- load this CTA's weight rows into SMEM (once) ----
    for (int i = tid * 4; i < 32 * 512; i += THREADS * 4) {
        int row  = i >> 9;                   // j_local*4 + gate
        int k    = i & 511;
        int grow = l * G4 + (row & 3) * HID + jbase + (row >> 2);
        *(float4*)&s_wx[i] = *(const float4*)&Wx[(size_t)grow * DIN + k];
        *(float4*)&s_wh[i] = *(const float4*)&Wh[(size_t)grow * HID + k];
    }
    if (tid < 32) {
        int grow = l * G4 + (tid & 3) * HID + jbase + (tid >> 2);
        s_bias[tid] = bx[grow] + bh[grow];
    }

    // ---- init state: (j, b=lane). Only group A maintains c/h. ----
    const int j = jbase + wj;
    float c_reg  = c0[(lane * LAYERS + l) * HID + j];
    float h_last = h0[(lane * LAYERS + l) * HID + j];
    if (grp == 0) {
        // both parities: g_h persists across graph replays (see R4 bug)
        __stcg(&g_h[l][0][j * BATCH + lane], h_last);
        __stcg(&g_h[l][1][j * BATCH + lane], h_last);
    }

    grid_barrier(1u);

    // ---- wavefront: phase p = layer0 step t=p AND layer1 step t=p-1 ----
    for (int p = 0; p <= SEQT; ++p) {
        const bool active = (l == 0) ? (p < SEQT) : (p >= 1);
        const int  t      = (l == 0) ? p : (p - 1);
        const int  rdpar  = (p + 1) & 1;
        const int  wrpar  = p & 1;

        const float* in0 = (l == 0) ? &g_xT[(size_t)t * DIN * BATCH]
                                    : &g_h[0][rdpar][0];
        const float* in1 = &g_h[l][rdpar][0];

        unsigned long long acc[8];           // 0..3 = X gates, 4..7 = H gates
        #pragma unroll
        for (int g = 0; g < 8; ++g) acc[g] = 0ull;

        // two chunk rounds of 128 k per group
        for (int r = 0; r < 2; ++r) {
            // ---- cooperative staging: 4 buffers, packed (k,k+1) pairs ----
            if (active) {
                #pragma unroll
                for (int q = tid; q < 2048; q += THREADS) {
                    int buf = q >> 9;                  // 0=in0A 1=in1A 2=in0B 3=in1B
                    int pj  = q & 511;
                    int kp  = pj >> 3;                 // pair index 0..63
                    int bg  = (pj & 7) << 2;           // batch group 0,4,..28
                    int ks  = ((buf >= 2) ? 256 : 0) + r * 128 + 2 * kp;
                    const float* src = ((buf & 1) ? in1 : in0) + ks * BATCH + bg;
                    float4 fa = __ldcg((const float4*)src);
                    float4 fb = __ldcg((const float4*)(src + BATCH));
                    float* dst = smem + OFF_BUF + buf * 4096 + (kp * 32 + bg) * 2;
                    *(float4*)(dst)     = make_float4(fa.x, fb.x, fa.y, fb.y);
                    *(float4*)(dst + 4) = make_float4(fa.z, fb.z, fa.w, fb.w);
                }
            }
            __syncthreads();

            // ---- compute: 128 k (64 pairs) from this group's buffers ----
            if (active) {
                const unsigned long long* in0p =
                    (const unsigned long long*)(smem + OFF_BUF + (grp * 2 + 0) * 4096);
                const unsigned long long* in1p =
                    (const unsigned long long*)(smem + OFF_BUF + (grp * 2 + 1) * 4096);
                const int kw0 = grp * 256 + r * 128;   // absolute k for weights
                #pragma unroll 4
                for (int i = 0; i < 32; ++i) {
                    const int kp2 = 2 * i;
                    unsigned long long p00 = in0p[(kp2 + 0) * 32 + lane];
                    unsigned long long p01 = in0p[(kp2 + 1) * 32 + lane];
                    unsigned long long p10 = in1p[(kp2 + 0) * 32 + lane];
                    unsigned long long p11 = in1p[(kp2 + 1) * 32 + lane];
                    const int kw = kw0 + 4 * i;
                    #pragma unroll
                    for (int g = 0; g < 4; ++g) {
                        const int row = (wj * 4 + g) << 9;
                        ull2 wx = *(const ull2*)&s_wx[row + kw];
                        ull2 wh = *(const ull2*)&s_wh[row + kw];
                        fma2(acc[g],     wx.x, p00);
                        fma2(acc[g],     wx.y, p01);
                        fma2(acc[g + 4], wh.x, p10);
                        fma2(acc[g + 4], wh.y, p11);
                    }
                }
            }
            __syncthreads();
        }

        // ---- cross-group reduction: B writes partials, A finalizes ----
        unsigned long long* red = (unsigned long long*)(smem + OFF_RED);
        if (active && grp == 1) {
            #pragma unroll
            for (int g = 0; g < 8; ++g)
                red[(wj * 8 + g) * 32 + lane] = acc[g];
        }
        __syncthreads();

        if (active && grp == 0) {
            float sum[8];
            #pragma unroll
            for (int g = 0; g < 8; ++g) {
                float2 a = u2f2(acc[g]);
                float2 b = u2f2(red[(wj * 8 + g) * 32 + lane]);
                sum[g] = (a.x + a.y) + (b.x + b.y);
            }
            float pre_i = sum[0] + sum[4] + s_bias[wj * 4 + 0];
            float pre_f = sum[1] + sum[5] + s_bias[wj * 4 + 1];
            float pre_g = sum[2] + sum[6] + s_bias[wj * 4 + 2];
            float pre_o = sum[3] + sum[7] + s_bias[wj * 4 + 3];

            float ig = sigmoidf_(pre_i);
            float fg = sigmoidf_(pre_f);
            float gg = tanhf(pre_g);
            float og = sigmoidf_(pre_o);

            c_reg  = fg * c_reg + ig * gg;
            float hN = og * tanhf(c_reg);
            h_last = hN;

            __stcg(&g_h[l][wrpar][j * BATCH + lane], hN);
            if (l == 1)
                out[((size_t)lane * SEQT + t) * HID + j] = hN;
        }

        grid_barrier((unsigned)(p + 2));
    }

    // ---- final h_n / c_n: [L][B][H] each, appended after output ----
    if (grp == 0 &&
        out_size >= BATCH * SEQT * HID + 2 * LAYERS * BATCH * HID) {
        float* hn = out + (size_t)BATCH * SEQT * HID;
        float* cn = hn + (size_t)LAYERS * BATCH * HID;
        hn[((size_t)l * BATCH + lane) * HID + j] = h_last;
        cn[((size_t)l * BATCH + lane) * HID + j] = c_reg;
    }
}

// ---------------- launch -----------------------------------------------------
extern "C" void kernel_launch(void* const* d_in, const int* in_sizes, int n_in,
                              void* d_out, int out_size) {
    const float* x  = (const float*)d_in[0];
    const float* h0 = (const float*)d_in[1];
    const float* c0 = (const float*)d_in[2];
    const float* Wx = (const float*)d_in[3];
    const float* bx = (const float*)d_in[4];
    const float* Wh = (const float*)d_in[5];
    const float* bh = (const float*)d_in[6];
    float* out = (float*)d_out;
    (void)in_sizes; (void)n_in;

    cudaFuncSetAttribute(lstm_persist,
                         cudaFuncAttributeMaxDynamicSharedMemorySize, SMEM_BYTES);

    reset_kernel<<<1, 1>>>();

    dim3 tb(32, 8);
    dim3 tg(SEQT, DIN / 32);
    transpose_x_kernel<<<tg, tb>>>(x);

    lstm_persist<<<NCTA, THREADS, SMEM_BYTES>>>(h0, c0, Wx, bx, Wh, bh, out, out_size);
}

// round 11
// speedup vs baseline: 1.1706x; 1.0614x over previous
#include <cuda_runtime.h>
#include <cstdint>
#include <math.h>

// Problem constants
#define BATCH   32
#define SEQT    512
#define DIN     512
#define HID     512
#define LAYERS  2
#define G4      (4*HID)

// Persistent-kernel config
#define NCTA    128              // 64 CTAs per layer
#define CPL     64               // CTAs per layer
#define THREADS 512              // 16 warps: warps 0-7 = k-half A, 8-15 = k-half B
#define JPC     8                // hidden indices per CTA

// SMEM float offsets
#define OFF_WX   0                       // [32 rows][512]
#define OFF_WH   16384
#define OFF_BUF  32768                   // 4 bufs x 4096 floats (packed pairs)
#define OFF_RED  (32768 + 16384)         // 4096 floats
#define OFF_BIAS (OFF_RED + 4096)
#define SMEM_FLOATS (OFF_BIAS + 32)
#define SMEM_BYTES  (SMEM_FLOATS * 4)

// ---------------- device scratch -------------------------------------------
__device__ float    g_xT[SEQT * DIN * BATCH];      // x transposed: [t][k][b]
__device__ float    g_h[LAYERS][2][HID * BATCH];   // ping-pong h per layer
__device__ unsigned g_arr[2];                      // per-layer arrive counters
__device__ unsigned g_rel[2];                      // per-layer release (cumulative gen)

// ---------------- transpose x + barrier reset (one launch) ------------------
__global__ void transpose_x_kernel(const float* __restrict__ x) {
    if (blockIdx.x == 0 && blockIdx.y == 0 &&
        threadIdx.x == 0 && threadIdx.y == 0) {
        g_arr[0] = 0u; g_arr[1] = 0u;
        g_rel[0] = 0u; g_rel[1] = 0u;
    }
    __shared__ float tile[32][33];
    int t  = blockIdx.x;
    int k0 = blockIdx.y * 32;
    int lx = threadIdx.x;
    for (int bb = threadIdx.y; bb < 32; bb += 8)
        tile[bb][lx] = x[((bb * SEQT + t) * DIN) + k0 + lx];
    __syncthreads();
    for (int kk = threadIdx.y; kk < 32; kk += 8)
        g_xT[(t * DIN + (k0 + kk)) * BATCH + lx] = tile[lx][kk];
}

// ---------------- helpers ----------------------------------------------------
// NOTE: "memory" clobber is load-bearing. Without it the compiler may hoist
// subsequent __ldcg data loads ABOVE a spin loop built on this read (R8 bug:
// layer-1 read stale layer-0 h because its g_h loads were hoisted past the
// RAW spin).
__device__ __forceinline__ unsigned ld_rel(const unsigned* p) {
    unsigned v;
    asm volatile("ld.global.cg.u32 %0, [%1];" : "=r"(v) : "l"(p) : "memory");
    return v;
}

// spin with HW-sleep backoff: ~50x less L2 poll traffic on the shared line
__device__ __forceinline__ void spin_until(const unsigned* p, unsigned need) {
    while (ld_rel(p) < need) { __nanosleep(64); }
}

// per-layer 64-CTA barrier, cumulative generation
__device__ __forceinline__ void layer_barrier(int l, unsigned gen) {
    __threadfence();
    __syncthreads();
    if (threadIdx.x == 0) {
        unsigned a = atomicAdd(&g_arr[l], 1u);
        if (a + 1u == gen * (unsigned)CPL) {
            atomicExch(&g_rel[l], gen);
        } else {
            spin_until(&g_rel[l], gen);
        }
        __threadfence();
    }
    __syncthreads();
}

__device__ __forceinline__ float sigmoidf_(float v) {
    return 1.0f / (1.0f + expf(-v));
}

// packed f32x2 FMA: d = a*b + d
__device__ __forceinline__ void fma2(unsigned long long& d,
                                     unsigned long long a,
                                     unsigned long long b) {
    asm("fma.rn.f32x2 %0, %1, %2, %0;" : "+l"(d) : "l"(a), "l"(b));
}
__device__ __forceinline__ float2 u2f2(unsigned long long v) {
    float2 f;
    asm("mov.b64 {%0, %1}, %2;" : "=f"(f.x), "=f"(f.y) : "l"(v));
    return f;
}

struct ull2 { unsigned long long x, y; };

// compute one 128-k round for this thread's group from staged SMEM
__device__ __forceinline__ void compute_round(const float* smem, int grp, int r,
                                              int wj, int lane,
                                              unsigned long long* acc) {
    const unsigned long long* in0p =
        (const unsigned long long*)(smem + OFF_BUF + (grp * 2 + 0) * 4096);
    const unsigned long long* in1p =
        (const unsigned long long*)(smem + OFF_BUF + (grp * 2 + 1) * 4096);
    const int kw0 = grp * 256 + r * 128;
    #pragma unroll 4
    for (int i = 0; i < 32; ++i) {
        const int kp2 = 2 * i;
        unsigned long long p00 = in0p[(kp2 + 0) * 32 + lane];
        unsigned long long p01 = in0p[(kp2 + 1) * 32 + lane];
        unsigned long long p10 = in1p[(kp2 + 0) * 32 + lane];
        unsigned long long p11 = in1p[(kp2 + 1) * 32 + lane];
        const int kw = kw0 + 4 * i;
        #pragma unroll
        for (int g = 0; g < 4; ++g) {
            const int row = (wj * 4 + g) << 9;
            ull2 wx = *(const ull2*)&smem[OFF_WX + row + kw];
            ull2 wh = *(const ull2*)&smem[OFF_WH + row + kw];
            fma2(acc[g],     wx.x, p00);
            fma2(acc[g],     wx.y, p01);
            fma2(acc[g + 4], wh.x, p10);
            fma2(acc[g + 4], wh.y, p11);
        }
    }
}

// ---------------- persistent LSTM kernel ------------------------------------
__global__ void __launch_bounds__(THREADS, 1)
lstm_persist(const float* __restrict__ h0,
             const float* __restrict__ c0,
             const float* __restrict__ Wx,   // [L][4H][D]
             const float* __restrict__ bx,
             const float* __restrict__ Wh,   // [L][4H][H]
             const float* __restrict__ bh,
             float* __restrict__ out,
             int out_size) {
    extern __shared__ float smem[];
    float* s_bias = smem + OFF_BIAS;

    const int cta   = blockIdx.x;
    const int l     = cta >> 6;              // layer 0/1
    const int jbase = (cta & 63) * JPC;
    const int tid   = threadIdx.x;
    const int w     = tid >> 5;              // 0..15
    const int lane  = tid & 31;              // batch index
    const int grp   = w >> 3;                // 0 = k[0,256), 1 = k[256,512)
    const int wj    = w & 7;                 // hidden index within CTA
    // finalize split: group A owns j 0-3, group B owns j 4-7
    const bool owner = (grp == 0) ? (wj < 4) : (wj >= 4);

    // ---- load this CTA's weight rows into SMEM (once) ----
    for (int i = tid * 4; i < 32 * 512; i += THREADS * 4) {
        int row  = i >> 9;
        int k    = i & 511;
        int grow = l * G4 + (row & 3) * HID + jbase + (row >> 2);
        *(float4*)&smem[OFF_WX + i] = *(const float4*)&Wx[(size_t)grow * DIN + k];
        *(float4*)&smem[OFF_WH + i] = *(const float4*)&Wh[(size_t)grow * HID + k];
    }
    if (tid < 32) {
        int grow = l * G4 + (tid & 3) * HID + jbase + (tid >> 2);
        s_bias[tid] = bx[grow] + bh[grow];
    }

    // ---- init state ----
    const int j = jbase + wj;
    float c_reg  = c0[(lane * LAYERS + l) * HID + j];
    float h_last = h0[(lane * LAYERS + l) * HID + j];
    if (owner) {
        // both parities: g_h persists across graph replays
        __stcg(&g_h[l][0][j * BATCH + lane], h_last);
        __stcg(&g_h[l][1][j * BATCH + lane], h_last);
    }

    layer_barrier(l, 1u);                    // init done within this layer

    // staging geometry: thread handles pair-index kp, batch group bg, all 4 bufs
    const int kp = tid >> 3;                 // 0..63
    const int bg = (tid & 7) << 2;           // 0,4,...,28
    unsigned long long* red = (unsigned long long*)(smem + OFF_RED);

    // ---- per-layer step loop (layer-1 trails via RAW wait; slack 2 steps) ----
    for (int t = 0; t < SEQT; ++t) {
        if (l == 1) {
            // RAW: need layer-0 step t complete -> g_rel[0] >= t+2
            spin_until(&g_rel[0], (unsigned)(t + 2));
            __syncthreads();   // compiler+exec barrier: no load may precede spin
        }
        const float* in0 = (l == 0) ? &g_xT[(size_t)t * DIN * BATCH]
                                    : &g_h[0][t & 1][0];
        const float* in1 = &g_h[l][(t + 1) & 1][0];

        unsigned long long acc[8];
        #pragma unroll
        for (int g = 0; g < 8; ++g) acc[g] = 0ull;

        float4 f[8];
        // ---- load round 0 ----
        #pragma unroll
        for (int b = 0; b < 4; ++b) {
            const float* src = ((b & 1) ? in1 : in0)
                             + (((b >= 2) ? 256 : 0) + 2 * kp) * BATCH + bg;
            f[2 * b]     = __ldcg((const float4*)src);
            f[2 * b + 1] = __ldcg((const float4*)(src + BATCH));
        }
        // ---- store round 0 to SMEM (packed pairs) ----
        #pragma unroll
        for (int b = 0; b < 4; ++b) {
            float4 fa = f[2 * b], fb = f[2 * b + 1];
            float* dst = smem + OFF_BUF + b * 4096 + (kp * 32 + bg) * 2;
            *(float4*)(dst)     = make_float4(fa.x, fb.x, fa.y, fb.y);
            *(float4*)(dst + 4) = make_float4(fa.z, fb.z, fa.w, fb.w);
        }
        __syncthreads();

        // ---- issue round-1 loads (latency hidden under round-0 compute) ----
        #pragma unroll
        for (int b = 0; b < 4; ++b) {
            const float* src = ((b & 1) ? in1 : in0)
                             + (((b >= 2) ? 256 : 0) + 128 + 2 * kp) * BATCH + bg;
            f[2 * b]     = __ldcg((const float4*)src);
            f[2 * b + 1] = __ldcg((const float4*)(src + BATCH));
        }

        compute_round(smem, grp, 0, wj, lane, acc);
        __syncthreads();

        // ---- store round 1, compute round 1 ----
        #pragma unroll
        for (int b = 0; b < 4; ++b) {
            float4 fa = f[2 * b], fb = f[2 * b + 1];
            float* dst = smem + OFF_BUF + b * 4096 + (kp * 32 + bg) * 2;
            *(float4*)(dst)     = make_float4(fa.x, fb.x, fa.y, fb.y);
            *(float4*)(dst + 4) = make_float4(fa.z, fb.z, fa.w, fb.w);
        }
        __syncthreads();

        compute_round(smem, grp, 1, wj, lane, acc);

        // ---- cross-group partials: non-owners publish ----
        if (!owner) {
            #pragma unroll
            for (int g = 0; g < 8; ++g)
                red[(wj * 8 + g) * 32 + lane] = acc[g];
        }
        // layer-0 WAR clearance overlapped with partial publication:
        // before overwriting g_h[0][t&1], layer-1 must be done reading it
        // (layer-1 step t-2 complete -> g_rel[1] >= t). Safe: followed by
        // __syncthreads (full barrier) before any h store.
        if (l == 0 && tid == 0 && t >= 2) {
            spin_until(&g_rel[1], (unsigned)t);
        }
        __syncthreads();

        if (owner) {
            float sum[8];
            #pragma unroll
            for (int g = 0; g < 8; ++g) {
                float2 a = u2f2(acc[g]);
                float2 b = u2f2(red[(wj * 8 + g) * 32 + lane]);
                sum[g] = (a.x + a.y) + (b.x + b.y);
            }
            float pre_i = sum[0] + sum[4] + s_bias[wj * 4 + 0];
            float pre_f = sum[1] + sum[5] + s_bias[wj * 4 + 1];
            float pre_g = sum[2] + sum[6] + s_bias[wj * 4 + 2];
            float pre_o = sum[3] + sum[7] + s_bias[wj * 4 + 3];

            float ig = sigmoidf_(pre_i);
            float fg = sigmoidf_(pre_f);
            float gg = tanhf(pre_g);
            float og = sigmoidf_(pre_o);

            c_reg  = fg * c_reg + ig * gg;
            float hN = og * tanhf(c_reg);
            h_last = hN;

            __stcg(&g_h[l][t & 1][j * BATCH + lane], hN);
            if (l == 1)
                out[((size_t)lane * SEQT + t) * HID + j] = hN;
        }

        layer_barrier(l, (unsigned)(t + 2));
    }

    // ---- final h_n / c_n: [L][B][H] each, appended after output ----
    if (owner &&
        out_size >= BATCH * SEQT * HID + 2 * LAYERS * BATCH * HID) {
        float* hn = out + (size_t)BATCH * SEQT * HID;
        float* cn = hn + (size_t)LAYERS * BATCH * HID;
        hn[((size_t)l * BATCH + lane) * HID + j] = h_last;
        cn[((size_t)l * BATCH + lane) * HID + j] = c_reg;
    }
}

// ---------------- launch -----------------------------------------------------
extern "C" void kernel_launch(void* const* d_in, const int* in_sizes, int n_in,
                              void* d_out, int out_size) {
    const float* x  = (const float*)d_in[0];
    const float* h0 = (const float*)d_in[1];
    const float* c0 = (const float*)d_in[2];
    const float* Wx = (const float*)d_in[3];
    const float* bx = (const float*)d_in[4];
    const float* Wh = (const float*)d_in[5];
    const float* bh = (const float*)d_in[6];
    float* out = (float*)d_out;
    (void)in_sizes; (void)n_in;

    cudaFuncSetAttribute(lstm_persist,
                         cudaFuncAttributeMaxDynamicSharedMemorySize, SMEM_BYTES);

    dim3 tb(32, 8);
    dim3 tg(SEQT, DIN / 32);
    transpose_x_kernel<<<tg, tb>>>(x);   // also resets barrier state

    lstm_persist<<<NCTA, THREADS, SMEM_BYTES>>>(h0, c0, Wx, bx, Wh, bh, out, out_size);
}

// round 13
// speedup vs baseline: 1.2901x; 1.1020x over previous
#include <cuda_runtime.h>
#include <cstdint>
#include <math.h>

// Problem constants
#define BATCH   32
#define SEQT    512
#define DIN     512
#define HID     512
#define LAYERS  2
#define G4      (4*HID)

// Persistent-kernel config
#define NCTA    128              // 64 CTAs per layer
#define CPL     64               // CTAs per layer
#define THREADS 512              // 16 warps = 4 j-pairs x 4 k-groups
#define JPC     8                // hidden indices per CTA

// SMEM float offsets
#define OFF_WX   0                       // [32 rows][512]
#define OFF_WH   16384
#define OFF_BUF  32768                   // 4 bufs x 4096 floats (packed pairs)
#define OFF_RED  OFF_BUF                 // reduction ALIASES act bufs (post-compute)
#define OFF_BIAS (OFF_BUF + 16384)
#define SMEM_FLOATS (OFF_BIAS + 32)
#define SMEM_BYTES  (SMEM_FLOATS * 4)    // ~196.7 KB

// ---------------- device scratch -------------------------------------------
__device__ float    g_xT[SEQT * DIN * BATCH];      // x transposed: [t][k][b]
__device__ float    g_h[LAYERS][2][HID * BATCH];   // ping-pong h per layer
__device__ unsigned g_arr[2];                      // per-layer arrive counters
__device__ unsigned g_rel[2];                      // per-layer release (cumulative gen)

// ---------------- transpose x + barrier reset (one launch) ------------------
__global__ void transpose_x_kernel(const float* __restrict__ x) {
    if (blockIdx.x == 0 && blockIdx.y == 0 &&
        threadIdx.x == 0 && threadIdx.y == 0) {
        g_arr[0] = 0u; g_arr[1] = 0u;
        g_rel[0] = 0u; g_rel[1] = 0u;
    }
    __shared__ float tile[32][33];
    int t  = blockIdx.x;
    int k0 = blockIdx.y * 32;
    int lx = threadIdx.x;
    for (int bb = threadIdx.y; bb < 32; bb += 8)
        tile[bb][lx] = x[((bb * SEQT + t) * DIN) + k0 + lx];
    __syncthreads();
    for (int kk = threadIdx.y; kk < 32; kk += 8)
        g_xT[(t * DIN + (k0 + kk)) * BATCH + lx] = tile[lx][kk];
}

// ---------------- helpers ----------------------------------------------------
// "memory" clobber is load-bearing (R8 bug: hoisted data loads past spin).
__device__ __forceinline__ unsigned ld_rel(const unsigned* p) {
    unsigned v;
    asm volatile("ld.global.cg.u32 %0, [%1];" : "=r"(v) : "l"(p) : "memory");
    return v;
}

__device__ __forceinline__ void spin_until(const unsigned* p, unsigned need) {
    while (ld_rel(p) < need) { __nanosleep(64); }
}

// per-layer 64-CTA barrier, cumulative generation
__device__ __forceinline__ void layer_barrier(int l, unsigned gen) {
    __threadfence();
    __syncthreads();
    if (threadIdx.x == 0) {
        unsigned a = atomicAdd(&g_arr[l], 1u);
        if (a + 1u == gen * (unsigned)CPL) {
            atomicExch(&g_rel[l], gen);
        } else {
            spin_until(&g_rel[l], gen);
        }
        __threadfence();
    }
    __syncthreads();
}

__device__ __forceinline__ float sigmoidf_(float v) {
    return 1.0f / (1.0f + expf(-v));
}

// packed f32x2 FMA: d = a*b + d
__device__ __forceinline__ void fma2(unsigned long long& d,
                                     unsigned long long a,
                                     unsigned long long b) {
    asm("fma.rn.f32x2 %0, %1, %2, %0;" : "+l"(d) : "l"(a), "l"(b));
}
__device__ __forceinline__ float2 u2f2(unsigned long long v) {
    float2 f;
    asm("mov.b64 {%0, %1}, %2;" : "=f"(f.x), "=f"(f.y) : "l"(v));
    return f;
}

struct ull2 { unsigned long long x, y; };

// One 64-k round slice for warp (p = j-pair, q = k-group), round r.
// acc[jj*8 + g*2 + m]: jj = j within pair, g = gate, m = 0:Wx 1:Wh.
__device__ __forceinline__ void compute_round(const float* smem, int r,
                                              int p, int q, int lane,
                                              unsigned long long* acc) {
    const unsigned long long* in0p =
        (const unsigned long long*)(smem + OFF_BUF + ((q >> 1) << 1) * 4096);
    const unsigned long long* in1p = in0p + 2048;   // next buf
    const int po  = (q & 1) << 5;                   // pair offset 0 or 32
    const int kw0 = r * 256 + q * 64;
    #pragma unroll 1
    for (int i = 0; i < 16; ++i) {
        const int pi = po + 2 * i;
        unsigned long long p00 = in0p[(pi + 0) * 32 + lane];
        unsigned long long p01 = in0p[(pi + 1) * 32 + lane];
        unsigned long long p10 = in1p[(pi + 0) * 32 + lane];
        unsigned long long p11 = in1p[(pi + 1) * 32 + lane];
        const int kw = kw0 + 4 * i;
        #pragma unroll
        for (int jj = 0; jj < 2; ++jj) {
            #pragma unroll
            for (int g = 0; g < 4; ++g) {
                const int row = ((((p << 1) | jj) << 2) | g) << 9;
                ull2 wx = *(const ull2*)&smem[OFF_WX + row + kw];
                ull2 wh = *(const ull2*)&smem[OFF_WH + row + kw];
                const int a = jj * 8 + g * 2;
                fma2(acc[a],     wx.x, p00);
                fma2(acc[a],     wx.y, p01);
                fma2(acc[a + 1], wh.x, p10);
                fma2(acc[a + 1], wh.y, p11);
            }
        }
    }
}

// ---------------- persistent LSTM kernel ------------------------------------
__global__ void __launch_bounds__(THREADS, 1)
lstm_persist(const float* __restrict__ h0,
             const float* __restrict__ c0,
             const float* __restrict__ Wx,   // [L][4H][D]
             const float* __restrict__ bx,
             const float* __restrict__ Wh,   // [L][4H][H]
             const float* __restrict__ bh,
             float* __restrict__ out,
             int out_size) {
    extern __shared__ float smem[];
    float* s_bias = smem + OFF_BIAS;

    const int cta   = blockIdx.x;
    const int l     = cta >> 6;              // layer 0/1
    const int jbase = (cta & 63) * JPC;
    const int tid   = threadIdx.x;
    const int w     = tid >> 5;              // 0..15
    const int lane  = tid & 31;              // batch index
    const int p_    = w & 3;                 // j-pair: j in {2p, 2p+1}
    const int q_    = w >> 2;                // k-group 0..3 (64-k slices)
    // finalize owners: warps 0..7; owner w handles j = 2*(w&3) + (w>>2)
    const bool owner = (w < 8);
    const int  jl    = owner ? ((w & 3) * 2 + (w >> 2)) : 0;
    const int  j     = jbase + jl;

    // ---- load this CTA's weight rows into SMEM (once) ----
    for (int i = tid * 4; i < 32 * 512; i += THREADS * 4) {
        int row  = i >> 9;                   // j_local*4 + gate
        int k    = i & 511;
        int grow = l * G4 + (row & 3) * HID + jbase + (row >> 2);
        *(float4*)&smem[OFF_WX + i] = *(const float4*)&Wx[(size_t)grow * DIN + k];
        *(float4*)&smem[OFF_WH + i] = *(const float4*)&Wh[(size_t)grow * HID + k];
    }
    if (tid < 32) {
        int grow = l * G4 + (tid & 3) * HID + jbase + (tid >> 2);
        s_bias[tid] = bx[grow] + bh[grow];   // s_bias[j*4 + g]
    }

    // ---- init state (owners only hold c/h) ----
    float c_reg  = c0[(lane * LAYERS + l) * HID + j];
    float h_last = h0[(lane * LAYERS + l) * HID + j];
    if (owner) {
        // both parities: g_h persists across graph replays
        __stcg(&g_h[l][0][j * BATCH + lane], h_last);
        __stcg(&g_h[l][1][j * BATCH + lane], h_last);
    }

    layer_barrier(l, 1u);

    // staging geometry: thread handles pair-index kp, batch group bg, 4 bufs
    const int kp = tid >> 3;                 // 0..63
    const int bg = (tid & 7) << 2;           // 0,4,...,28

    // ---- per-layer step loop (layer-1 trails via RAW wait; 2-step slack) ----
    for (int t = 0; t < SEQT; ++t) {
        if (l == 1) {
            spin_until(&g_rel[0], (unsigned)(t + 2));  // RAW: layer-0 step t done
            __syncthreads();   // no data load may precede the spin
        }
        const float* in0 = (l == 0) ? &g_xT[(size_t)t * DIN * BATCH]
                                    : &g_h[0][t & 1][0];
        const float* in1 = &g_h[l][(t + 1) & 1][0];

        unsigned long long acc[16];
        #pragma unroll
        for (int g = 0; g < 16; ++g) acc[g] = 0ull;

        float4 f[8];
        // ---- load + store round 0: bufs {0,1}=k[r256,+128), {2,3}=[+128,+256)
        #pragma unroll
        for (int b = 0; b < 4; ++b) {
            const float* src = ((b & 1) ? in1 : in0)
                             + (((b >> 1) ? 128 : 0) + 2 * kp) * BATCH + bg;
            f[2 * b]     = __ldcg((const float4*)src);
            f[2 * b + 1] = __ldcg((const float4*)(src + BATCH));
        }
        #pragma unroll
        for (int b = 0; b < 4; ++b) {
            float4 fa = f[2 * b], fb = f[2 * b + 1];
            float* dst = smem + OFF_BUF + b * 4096 + (kp * 32 + bg) * 2;
            *(float4*)(dst)     = make_float4(fa.x, fb.x, fa.y, fb.y);
            *(float4*)(dst + 4) = make_float4(fa.z, fb.z, fa.w, fb.w);
        }
        __syncthreads();

        // ---- issue round-1 loads (hidden under round-0 compute) ----
        #pragma unroll
        for (int b = 0; b < 4; ++b) {
            const float* src = ((b & 1) ? in1 : in0)
                             + (256 + ((b >> 1) ? 128 : 0) + 2 * kp) * BATCH + bg;
            f[2 * b]     = __ldcg((const float4*)src);
            f[2 * b + 1] = __ldcg((const float4*)(src + BATCH));
        }

        compute_round(smem, 0, p_, q_, lane, acc);
        __syncthreads();

        #pragma unroll
        for (int b = 0; b < 4; ++b) {
            float4 fa = f[2 * b], fb = f[2 * b + 1];
            float* dst = smem + OFF_BUF + b * 4096 + (kp * 32 + bg) * 2;
            *(float4*)(dst)     = make_float4(fa.x, fb.x, fa.y, fb.y);
            *(float4*)(dst + 4) = make_float4(fa.z, fb.z, fa.w, fb.w);
        }
        __syncthreads();

        compute_round(smem, 1, p_, q_, lane, acc);
        __syncthreads();      // bufs free before red aliases onto them

        // ---- publish k-group partials: red[(row*32+lane)*9 + m*4 + q] ----
        // stride 9 floats across lanes -> conflict-free (gcd(9,32)=1)
        #pragma unroll
        for (int idx = 0; idx < 16; ++idx) {
            float2 a = u2f2(acc[idx]);
            const int jj = idx >> 3, g = (idx >> 1) & 3, m = idx & 1;
            const int row = ((p_ << 1) | jj) * 4 + g;
            smem[OFF_RED + (row * 32 + lane) * 9 + m * 4 + q_] = a.x + a.y;
        }
        // layer-0 WAR clearance (overlapped): layer-1 must be done reading
        // g_h[0][t&1] (its step t-2 complete). Followed by __syncthreads.
        if (l == 0 && tid == 0 && t >= 2) {
            spin_until(&g_rel[1], (unsigned)t);
        }
        __syncthreads();

        if (owner) {
            float pre[4];
            #pragma unroll
            for (int g = 0; g < 4; ++g) {
                const float* rp = &smem[OFF_RED + ((jl * 4 + g) * 32 + lane) * 9];
                float s = ((rp[0] + rp[1]) + (rp[2] + rp[3]))
                        + ((rp[4] + rp[5]) + (rp[6] + rp[7]));
                pre[g] = s + s_bias[(jl << 2) | g];
            }
            float ig = sigmoidf_(pre[0]);
            float fg = sigmoidf_(pre[1]);
            float gg = tanhf(pre[2]);
            float og = sigmoidf_(pre[3]);

            c_reg  = fg * c_reg + ig * gg;
            float hN = og * tanhf(c_reg);
            h_last = hN;

            __stcg(&g_h[l][t & 1][j * BATCH + lane], hN);
            if (l == 1)
                out[((size_t)lane * SEQT + t) * HID + j] = hN;
        }

        layer_barrier(l, (unsigned)(t + 2));
    }

    // ---- final h_n / c_n: [L][B][H] each, appended after output ----
    if (owner &&
        out_size >= BATCH * SEQT * HID + 2 * LAYERS * BATCH * HID) {
        float* hn = out + (size_t)BATCH * SEQT * HID;
        float* cn = hn + (size_t)LAYERS * BATCH * HID;
        hn[((size_t)l * BATCH + lane) * HID + j] = h_last;
        cn[((size_t)l * BATCH + lane) * HID + j] = c_reg;
    }
}

// ---------------- launch -----------------------------------------------------
extern "C" void kernel_launch(void* const* d_in, const int* in_sizes, int n_in,
                              void* d_out, int out_size) {
    const float* x  = (const float*)d_in[0];
    const float* h0 = (const float*)d_in[1];
    const float* c0 = (const float*)d_in[2];
    const float* Wx = (const float*)d_in[3];
    const float* bx = (const float*)d_in[4];
    const float* Wh = (const float*)d_in[5];
    const float* bh = (const float*)d_in[6];
    float* out = (float*)d_out;
    (void)in_sizes; (void)n_in;

    cudaFuncSetAttribute(lstm_persist,
                         cudaFuncAttributeMaxDynamicSharedMemorySize, SMEM_BYTES);

    dim3 tb(32, 8);
    dim3 tg(SEQT, DIN / 32);
    transpose_x_kernel<<<tg, tb>>>(x);   // also resets barrier state

    lstm_persist<<<NCTA, THREADS, SMEM_BYTES>>>(h0, c0, Wx, bx, Wh, bh, out, out_size);
}